// round 14
// baseline (speedup 1.0000x reference)
#include <cuda_runtime.h>

#define W 512
#define PLANE (512*512)
#define NPLANES 32
#define HALF 16
#define TOTAL (NPLANES*PLANE)
#define GP 524                  // padded pitch (6 + 512 + 6)
#define GR 524
#define PSZ (GP*GR)
#define BOFF (6*GP + 6)         // offset of pixel (0,0) in a padded plane
#define NT 256
#define NBLOCKS 2048
#define BIGF 1e30f

// Scratch (device globals; no allocation allowed)
__device__ __align__(16) float g_bufA[NPLANES * PSZ];
__device__ __align__(16) float g_bufB[NPLANES * PSZ];
__device__ __align__(16) float g_skel[TOTAL];
__device__ float g_part[NBLOCKS * 8];

// ---------------------------------------------------------------------------
// Packed f32x2 helpers (PTX-only packed fp32; sm_100+)
// ---------------------------------------------------------------------------
__device__ __forceinline__ unsigned long long pk2(float a, float b) {
    unsigned long long r;
    asm("mov.b64 %0, {%1, %2};" : "=l"(r) : "f"(a), "f"(b));
    return r;
}
__device__ __forceinline__ float2 upk2(unsigned long long v) {
    float a, b;
    asm("mov.b64 {%0, %1}, %2;" : "=f"(a), "=f"(b) : "l"(v));
    return make_float2(a, b);
}
__device__ __forceinline__ unsigned long long fma2_(unsigned long long a,
                                                    unsigned long long b,
                                                    unsigned long long c) {
    unsigned long long d;
    asm("fma.rn.f32x2 %0, %1, %2, %3;" : "=l"(d) : "l"(a), "l"(b), "l"(c));
    return d;
}
__device__ __forceinline__ unsigned long long mul2_(unsigned long long a,
                                                    unsigned long long b) {
    unsigned long long d;
    asm("mul.rn.f32x2 %0, %1, %2;" : "=l"(d) : "l"(a), "l"(b));
    return d;
}
__device__ __forceinline__ float rcpa(float x) {
    float r; asm("rcp.approx.ftz.f32 %0, %1;" : "=f"(r) : "f"(x)); return r;
}
__device__ __forceinline__ float ex2a(float x) {
    float r; asm("ex2.approx.ftz.f32 %0, %1;" : "=f"(r) : "f"(x)); return r;
}

// Pairwise gelu via Abramowitz-Stegun 7.1.26 erf (abs err <= 1.5e-7).
__device__ __forceinline__ float2 gelu2(float x0, float x1) {
    const float t0 = fabsf(x0) * 0.70710678118654752f;
    const float t1 = fabsf(x1) * 0.70710678118654752f;
    const float k0 = rcpa(fmaf(0.3275911f, t0, 1.0f));
    const float k1 = rcpa(fmaf(0.3275911f, t1, 1.0f));
    const unsigned long long kp = pk2(k0, k1);
    const unsigned long long tp = pk2(t0, t1);
    unsigned long long p = fma2_(pk2(-1.061405429f, -1.061405429f), kp,
                                 pk2(1.453152027f, 1.453152027f));
    p = fma2_(p, kp, pk2(-1.421413741f, -1.421413741f));
    p = fma2_(p, kp, pk2(0.284496736f, 0.284496736f));
    p = fma2_(p, kp, pk2(-0.254829592f, -0.254829592f));
    p = mul2_(p, kp);
    unsigned long long u = mul2_(tp, tp);
    u = mul2_(u, pk2(-1.4426950408889634f, -1.4426950408889634f));
    const float2 uf = upk2(u);
    const unsigned long long ep = pk2(ex2a(uf.x), ex2a(uf.y));
    const float2 ef = upk2(fma2_(p, ep, pk2(1.0f, 1.0f)));
    const float h0 = 0.5f * x0, h1 = 0.5f * x1;
    return make_float2(fmaf(fabsf(h0), ef.x, h0), fmaf(fabsf(h1), ef.y, h1));
}

// ---------------------------------------------------------------------------
// Fill ONLY the 6-wide halo rings of both padded buffers with +BIG.
// ---------------------------------------------------------------------------
__global__ __launch_bounds__(64) void fill_ring_kernel() {
    const int row = blockIdx.x;
    const int plane = blockIdx.y;
    float* base = (blockIdx.z ? g_bufB : g_bufA) + plane * PSZ + row * GP;
    if (row < 6 || row >= 518) {
        for (int c = threadIdx.x; c < GP; c += 64) base[c] = BIGF;
    } else {
        const int tx = threadIdx.x;
        if (tx < 6) base[tx] = BIGF;
        else if (tx < 12) base[512 + tx] = BIGF;
    }
}

// ---------------------------------------------------------------------------
// erode_quad: in (DIN x DIN, pitch PIN, halo HOUT+1) ->
//             out (DIN-2 x DIN-2, pitch POUT, halo HOUT).
// Each thread: 4 output columns (j=4*tx16), rolling 3x8 float4 window.
// ---------------------------------------------------------------------------
template<int DIN, int PIN, int HOUT, int POUT, bool BORDER>
__device__ __forceinline__ void erode_quad(const float* __restrict__ in,
                                           float* __restrict__ out,
                                           int by, int bx, int tx16, int ty16, int tid) {
    constexpr int DOUT = DIN - 2;
    constexpr int RPT = (DOUT + 15) / 16;
    const int j = 4 * tx16;
    const int r0 = ty16 * RPT;
    int r1 = r0 + RPT; if (r1 > DOUT) r1 = DOUT;
    const int rb = (r0 < DOUT) ? r0 : 0;    // safe row for (possibly idle) setup
    const float* pin = in + rb * PIN + j;
    float4 a0 = *(const float4*)(pin),       a1 = *(const float4*)(pin + 4);
    float4 b0 = *(const float4*)(pin + PIN), b1 = *(const float4*)(pin + PIN + 4);
    const float* nrow = pin + 2 * PIN;
    float* orow = out + rb * POUT + j;
    bool ok0 = true, ok1 = true, ok2 = true, ok3 = true;
    if (BORDER) {
        ok0 = (unsigned)(bx + j     - HOUT) < 512u;
        ok1 = (unsigned)(bx + j + 1 - HOUT) < 512u;
        ok2 = (unsigned)(bx + j + 2 - HOUT) < 512u;
        ok3 = (unsigned)(bx + j + 3 - HOUT) < 512u;
    }
    for (int i = r0; i < r1; ++i) {
        const float4 c0 = *(const float4*)(nrow), c1 = *(const float4*)(nrow + 4);
        const float vm1 = fminf(fminf(a0.y, b0.y), c0.y);
        const float vm2 = fminf(fminf(a0.z, b0.z), c0.z);
        const float vm3 = fminf(fminf(a0.w, b0.w), c0.w);
        const float vm4 = fminf(fminf(a1.x, b1.x), c1.x);
        float o0 = fminf(vm1, fminf(b0.x, b0.z));
        float o1 = fminf(vm2, fminf(b0.y, b0.w));
        float o2 = fminf(vm3, fminf(b0.z, b1.x));
        float o3 = fminf(vm4, fminf(b0.w, b1.y));
        if (BORDER) {
            const bool rok = (unsigned)(by + i - HOUT) < 512u;
            if (!rok | !ok0) o0 = BIGF;
            if (!rok | !ok1) o1 = BIGF;
            if (!rok | !ok2) o2 = BIGF;
            if (!rok | !ok3) o3 = BIGF;
        }
        *(float4*)orow = make_float4(o0, o1, o2, o3);
        a0 = b0; a1 = b1; b0 = c0; b1 = c1;
        nrow += PIN; orow += POUT;
    }
    // extra cols 64..DOUT-1 (scalar, scattered)
    constexpr int EX = (DOUT - 64) * DOUT;
    for (int e = tid; e < EX; e += NT) {
        const int q = e / DOUT, jj = 64 + q, i = e - q * DOUT;
        float v = fminf(fminf(in[i * PIN + jj + 1], in[(i + 1) * PIN + jj + 1]),
                        in[(i + 2) * PIN + jj + 1]);
        v = fminf(v, fminf(in[(i + 1) * PIN + jj], in[(i + 1) * PIN + jj + 2]));
        if (BORDER) {
            const int gr = by + i - HOUT, gc = bx + jj - HOUT;
            if ((unsigned)gr >= 512u || (unsigned)gc >= 512u) v = BIGF;
        }
        out[i * POUT + jj] = v;
    }
}

// ---------------------------------------------------------------------------
// upd: delta = gelu(Ek - dilate(Ek1)); INIT: sk = delta; else sk += gelu(d - sk*d)
// ek: halo HK, pitch PK.  ek1: halo H1 = HK-1, pitch PK1. float2 pairs.
// ---------------------------------------------------------------------------
template<int PK, int HK, int PK1, int H1, bool BORDER, bool INIT>
__device__ __forceinline__ void upd_pair(const float* __restrict__ ek,
                                         const float* __restrict__ ek1,
                                         float2* sk, int by, int bx, int tx, int ty) {
    const int j = 2 * tx, r0 = ty * 8;
    bool okL = true, okR = true;
    if (BORDER) {
        okL = (unsigned)(bx + j - 1) < 512u;
        okR = (unsigned)(bx + j + 2) < 512u;
    }
    auto rowpair = [&](int ri, bool rok) -> float2 {
        const float* p = ek1 + ri * PK1 + (j + H1 - 1);
        float v0, v1, v2, v3;
        if constexpr ((H1 & 1) == 1) {
            const float2 u = *(const float2*)(p);
            const float2 w = *(const float2*)(p + 2);
            v0 = u.x; v1 = u.y; v2 = w.x; v3 = w.y;
        } else {
            const float2 u = *(const float2*)(p + 1);
            v0 = p[0]; v1 = u.x; v2 = u.y; v3 = p[3];
        }
        if (BORDER) { if (!okL) v0 = -BIGF; if (!okR) v3 = -BIGF; }
        const float m = fmaxf(v1, v2);
        float2 rm = make_float2(fmaxf(m, v0), fmaxf(m, v3));
        if (BORDER && !rok) { rm.x = -BIGF; rm.y = -BIGF; }
        return rm;
    };
    float2 rma = rowpair(r0 + H1 - 1, !BORDER || ((unsigned)(by + r0 - 1) < 512u));
    float2 rmb = rowpair(r0 + H1, true);
    #pragma unroll
    for (int q = 0; q < 8; ++q) {
        const int r = r0 + q;
        const float2 rmc = rowpair(r + H1 + 1, !BORDER || ((unsigned)(by + r + 1) < 512u));
        const float o0 = fmaxf(fmaxf(rma.x, rmb.x), rmc.x);
        const float o1 = fmaxf(fmaxf(rma.y, rmb.y), rmc.y);
        const float* pc = ek + (r + HK) * PK + (j + HK);
        float e0, e1;
        if constexpr ((HK & 1) == 0) { const float2 u = *(const float2*)pc; e0 = u.x; e1 = u.y; }
        else { e0 = pc[0]; e1 = pc[1]; }
        const float2 d = gelu2(e0 - o0, e1 - o1);
        if (INIT) {
            sk[q] = d;
        } else {
            float s0 = sk[q].x, s1 = sk[q].y;
            const float2 g = gelu2(d.x - s0 * d.x, d.y - s1 * d.y);
            sk[q] = make_float2(s0 + g.x, s1 + g.y);
        }
        rma = rmb; rmb = rmc;
    }
}

__device__ __forceinline__ float warpSum(float v) {
    #pragma unroll
    for (int o = 16; o; o >>= 1) v += __shfl_down_sync(0xffffffffu, v, o);
    return v;
}

// ---------------------------------------------------------------------------
// Fused body. Stage layout (dims x dims @ pitch):
//   X : 76x76 @76 (sX)   E1: 74x74 @76 (sY)   E2: 72x72 @72 (sX)
//   E3: 70x70 @72 (sY)   E4: 68x68 @68 (sX)   E5: 66x66 @68 (sY)
// ---------------------------------------------------------------------------
template<bool BORDER, bool RED, bool INIT>
__device__ __forceinline__ void fused_body(const float* __restrict__ sp,
                                           const float* __restrict__ raw,
                                           float* __restrict__ dp,
                                           const float* __restrict__ yt,
                                           const float* __restrict__ yp,
                                           float* sX, float* sY, float* s_red,
                                           int plane, int by, int bx, int tid) {
    const int tx = tid & 31, ty = tid >> 5;     // pair mapping (32x8)
    const int tx16 = tid & 15, ty16 = tid >> 4; // quad mapping (16x16)

    // Load x with halo 6 into sX (pitch 76).
    if (INIT) {
        for (int r = ty; r < 76; r += 8) {
            float* srow = sX + r * 76;
            const int gr = by + r - 6;
            if (!BORDER) {
                const float* grp = raw + gr * W + bx - 6;
                *(float2*)(srow + 2 * tx) = *(const float2*)(grp + 2 * tx);
                if (tx < 6) *(float2*)(srow + 64 + 2 * tx) = *(const float2*)(grp + 64 + 2 * tx);
            } else {
                const bool rok = (unsigned)gr < 512u;
                {
                    const int gc = bx + 2 * tx - 6;
                    float v0 = BIGF, v1 = BIGF;
                    if (rok) {
                        if ((unsigned)gc < 512u) v0 = raw[gr * W + gc];
                        if ((unsigned)(gc + 1) < 512u) v1 = raw[gr * W + gc + 1];
                    }
                    *(float2*)(srow + 2 * tx) = make_float2(v0, v1);
                }
                if (tx < 6) {
                    const int gc = bx + 58 + 2 * tx;
                    float v0 = BIGF, v1 = BIGF;
                    if (rok) {
                        if ((unsigned)gc < 512u) v0 = raw[gr * W + gc];
                        if ((unsigned)(gc + 1) < 512u) v1 = raw[gr * W + gc + 1];
                    }
                    *(float2*)(srow + 64 + 2 * tx) = make_float2(v0, v1);
                }
            }
        }
    } else {
        const float* g0 = sp + (by - 6) * GP + (bx - 6);
        for (int r = ty; r < 76; r += 8) {
            const float2* grp = (const float2*)(g0 + r * GP);
            float2* srow = (float2*)(sX + r * 76);
            srow[tx] = grp[tx];
            if (tx < 6) srow[tx + 32] = grp[tx + 32];
        }
    }
    __syncthreads();

    erode_quad<76, 76, 5, 76, BORDER>(sX, sY, by, bx, tx16, ty16, tid);   // E1
    __syncthreads();

    float2 sk[8];
    const int r0 = ty * 8, j = 2 * tx;

    if (INIT) {
        // skel = gelu(X - dilate(E1)); X @sX(76,h6), E1 @sY(p76,h5)
        upd_pair<76, 6, 76, 5, BORDER, true>(sX, sY, sk, by, bx, tx, ty);
        __syncthreads();          // before E2 overwrites sX
    }

    erode_quad<74, 76, 4, 72, BORDER>(sY, sX, by, bx, tx16, ty16, tid);   // E2
    __syncthreads();

    if (!INIT) {
        const float* gs = &g_skel[plane * PLANE + (by + r0) * W + bx + j];
        #pragma unroll
        for (int q = 0; q < 8; ++q) sk[q] = *(const float2*)(gs + q * W);
    }
    upd_pair<76, 5, 72, 4, BORDER, false>(sY, sX, sk, by, bx, tx, ty);    // step 1
    __syncthreads();
    erode_quad<72, 72, 3, 72, BORDER>(sX, sY, by, bx, tx16, ty16, tid);   // E3
    __syncthreads();
    upd_pair<72, 4, 72, 3, BORDER, false>(sX, sY, sk, by, bx, tx, ty);    // step 2
    __syncthreads();
    erode_quad<70, 72, 2, 68, BORDER>(sY, sX, by, bx, tx16, ty16, tid);   // E4
    __syncthreads();
    upd_pair<72, 3, 68, 2, BORDER, false>(sY, sX, sk, by, bx, tx, ty);    // step 3
    __syncthreads();
    erode_quad<68, 68, 1, 68, BORDER>(sX, sY, by, bx, tx16, ty16, tid);   // E5
    __syncthreads();
    upd_pair<68, 2, 68, 1, BORDER, false>(sX, sY, sk, by, bx, tx, ty);    // step 4

    if (!RED) {
        float* gs = &g_skel[plane * PLANE + (by + r0) * W + bx + j];
        float* gd = dp + (by + r0) * GP + bx + j;
        #pragma unroll
        for (int q = 0; q < 8; ++q) {
            *(float2*)(gs + q * W) = sk[q];
            *(float2*)(gd + q * GP) = *(const float2*)(sX + (r0 + q + 2) * 68 + j + 2);
        }
    } else {
        float a0 = 0.f, a1 = 0.f, a2 = 0.f, a3 = 0.f, a4 = 0.f, a5 = 0.f, a6 = 0.f;
        const int gi0 = (plane & 15) * PLANE + (by + r0) * W + bx + j;
        if (plane < HALF) {
            #pragma unroll
            for (int q = 0; q < 8; ++q) {
                const float2 t = *(const float2*)(yt + gi0 + q * W);
                const float2 p = *(const float2*)(yp + gi0 + q * W);
                const float2 s = sk[q];
                a0 += t.x + t.y;
                a1 += p.x + p.y;
                a2 += t.x * p.x + t.y * p.y;
                a3 += s.x + s.y;
                a4 += s.x * t.x + s.y * t.y;
            }
        } else {
            #pragma unroll
            for (int q = 0; q < 8; ++q) {
                const float2 p = *(const float2*)(yp + gi0 + q * W);
                const float2 s = sk[q];
                a5 += s.x + s.y;
                a6 += s.x * p.x + s.y * p.y;
            }
        }
        float v[7] = {a0, a1, a2, a3, a4, a5, a6};
        const int lane = tid & 31, wrp = tid >> 5;
        #pragma unroll
        for (int k = 0; k < 7; k++) {
            const float s = warpSum(v[k]);
            if (lane == 0) s_red[wrp * 8 + k] = s;
        }
        __syncthreads();
        if (wrp == 0) {
            const int bid = plane * 64 + (by >> 6) * 8 + (bx >> 6);
            #pragma unroll
            for (int k = 0; k < 7; k++) {
                float s = (lane < 8) ? s_red[lane * 8 + k] : 0.f;
                s = warpSum(s);
                if (lane == 0) g_part[bid * 8 + k] = s;
            }
        }
    }
}

// ---------------------------------------------------------------------------
// Kernel wrappers
// ---------------------------------------------------------------------------
__global__ __launch_bounds__(NT, 5) void fused_init_kernel(const float* __restrict__ yt,
                                                           const float* __restrict__ yp) {
    __shared__ __align__(16) float sX[76 * 76];
    __shared__ __align__(16) float sY[74 * 76];
    const int plane = blockIdx.z;
    const float* raw = ((plane < HALF) ? yp : yt) + (plane & 15) * PLANE;
    const int by = blockIdx.y * 64, bx = blockIdx.x * 64;
    float* dp = g_bufA + plane * PSZ + BOFF;
    const bool border = (blockIdx.x == 0) | (blockIdx.x == 7) | (blockIdx.y == 0) | (blockIdx.y == 7);
    if (border) fused_body<true , false, true>(nullptr, raw, dp, nullptr, nullptr, sX, sY, nullptr,
                                               plane, by, bx, threadIdx.x);
    else        fused_body<false, false, true>(nullptr, raw, dp, nullptr, nullptr, sX, sY, nullptr,
                                               plane, by, bx, threadIdx.x);
}

__global__ __launch_bounds__(NT, 5) void fused_kernel(int readA) {
    __shared__ __align__(16) float sX[76 * 76];
    __shared__ __align__(16) float sY[74 * 76];
    const float* src = readA ? g_bufA : g_bufB;
    float* dst = readA ? g_bufB : g_bufA;
    const int plane = blockIdx.z;
    const int by = blockIdx.y * 64, bx = blockIdx.x * 64;
    const float* sp = src + plane * PSZ + BOFF;
    float* dp = dst + plane * PSZ + BOFF;
    const bool border = (blockIdx.x == 0) | (blockIdx.x == 7) | (blockIdx.y == 0) | (blockIdx.y == 7);
    if (border) fused_body<true , false, false>(sp, nullptr, dp, nullptr, nullptr, sX, sY, nullptr,
                                                plane, by, bx, threadIdx.x);
    else        fused_body<false, false, false>(sp, nullptr, dp, nullptr, nullptr, sX, sY, nullptr,
                                                plane, by, bx, threadIdx.x);
}

__global__ __launch_bounds__(NT, 5) void fused_red_kernel(const float* __restrict__ yt,
                                                          const float* __restrict__ yp,
                                                          int readA) {
    __shared__ __align__(16) float sX[76 * 76];
    __shared__ __align__(16) float sY[74 * 76];
    __shared__ float s_red[64];
    const float* src = readA ? g_bufA : g_bufB;
    float* dst = readA ? g_bufB : g_bufA;
    const int plane = blockIdx.z;
    const int by = blockIdx.y * 64, bx = blockIdx.x * 64;
    const float* sp = src + plane * PSZ + BOFF;
    float* dp = dst + plane * PSZ + BOFF;
    const bool border = (blockIdx.x == 0) | (blockIdx.x == 7) | (blockIdx.y == 0) | (blockIdx.y == 7);
    if (border) fused_body<true , true, false>(sp, nullptr, dp, yt, yp, sX, sY, s_red,
                                               plane, by, bx, threadIdx.x);
    else        fused_body<false, true, false>(sp, nullptr, dp, yt, yp, sX, sY, s_red,
                                               plane, by, bx, threadIdx.x);
}

// ---------------------------------------------------------------------------
// Final: sum 2048 partials, compute loss scalar
// ---------------------------------------------------------------------------
__global__ __launch_bounds__(256) void final_kernel(float* __restrict__ out) {
    float a[7] = {0.f, 0.f, 0.f, 0.f, 0.f, 0.f, 0.f};
    for (int b = threadIdx.x; b < NBLOCKS; b += 256) {
        #pragma unroll
        for (int j = 0; j < 7; j++) a[j] += g_part[b * 8 + j];
    }
    __shared__ float shm[8][8];
    const int lane = threadIdx.x & 31, wrp = threadIdx.x >> 5;
    #pragma unroll
    for (int j = 0; j < 7; j++) {
        const float v = warpSum(a[j]);
        if (lane == 0) shm[wrp][j] = v;
    }
    __syncthreads();
    if (wrp == 0) {
        float res[7];
        #pragma unroll
        for (int j = 0; j < 7; j++) {
            float v = (lane < 8) ? shm[lane][j] : 0.f;
            res[j] = warpSum(v);
        }
        if (lane == 0) {
            const float S_t = res[0], S_p = res[1], S_tp = res[2];
            const float S_sp = res[3], S_spt = res[4];
            const float S_st = res[5], S_stp = res[6];
            const float dice  = 1.0f - (2.0f * S_tp + 1.0f) / (S_t + S_p + 1.0f);
            const float tprec = (S_spt + 1.0f) / (S_sp + 1.0f);
            const float tsens = (S_stp + 1.0f) / (S_st + 1.0f);
            const float cl    = 1.0f - 2.0f * (tprec * tsens) / (tprec + tsens);
            out[0] = 0.7f * dice + 0.3f * cl;
        }
    }
}

// ---------------------------------------------------------------------------
extern "C" void kernel_launch(void* const* d_in, const int* in_sizes, int n_in,
                              void* d_out, int out_size) {
    const float* y_true = (const float*)d_in[0];
    const float* y_pred = (const float*)d_in[1];

    dim3 grid(8, 8, NPLANES);
    dim3 blk(NT);

    fill_ring_kernel<<<dim3(GR, NPLANES, 2), 64>>>();
    fused_init_kernel<<<grid, blk>>>(y_true, y_pred);    // init + steps 1-4  -> A
    fused_kernel<<<grid, blk>>>(1);                      // steps 5-8   A -> B
    fused_kernel<<<grid, blk>>>(0);                      // steps 9-12  B -> A
    fused_kernel<<<grid, blk>>>(1);                      // steps 13-16 A -> B
    fused_red_kernel<<<grid, blk>>>(y_true, y_pred, 0);  // steps 17-20 + sums (reads B)
    final_kernel<<<1, 256>>>((float*)d_out);
}

// round 15
// speedup vs baseline: 1.0546x; 1.0546x over previous
#include <cuda_runtime.h>

#define W 512
#define PLANE (512*512)
#define NPLANES 32
#define HALF 16
#define TOTAL (NPLANES*PLANE)
#define GP 524                  // padded pitch (6 + 512 + 6)
#define GR 524
#define PSZ (GP*GR)
#define BOFF (6*GP + 6)         // offset of pixel (0,0) in a padded plane
#define NT 512
#define NBLOCKS 2048
#define BIGF 1e30f

// Scratch (device globals; no allocation allowed)
__device__ __align__(16) float g_bufA[NPLANES * PSZ];
__device__ __align__(16) float g_bufB[NPLANES * PSZ];
__device__ __align__(16) float g_skel[TOTAL];
__device__ float g_part[NBLOCKS * 8];

// ---------------------------------------------------------------------------
// Packed f32x2 helpers (PTX-only packed fp32; sm_100+)
// ---------------------------------------------------------------------------
__device__ __forceinline__ unsigned long long pk2(float a, float b) {
    unsigned long long r;
    asm("mov.b64 %0, {%1, %2};" : "=l"(r) : "f"(a), "f"(b));
    return r;
}
__device__ __forceinline__ float2 upk2(unsigned long long v) {
    float a, b;
    asm("mov.b64 {%0, %1}, %2;" : "=f"(a), "=f"(b) : "l"(v));
    return make_float2(a, b);
}
__device__ __forceinline__ unsigned long long fma2_(unsigned long long a,
                                                    unsigned long long b,
                                                    unsigned long long c) {
    unsigned long long d;
    asm("fma.rn.f32x2 %0, %1, %2, %3;" : "=l"(d) : "l"(a), "l"(b), "l"(c));
    return d;
}
__device__ __forceinline__ unsigned long long mul2_(unsigned long long a,
                                                    unsigned long long b) {
    unsigned long long d;
    asm("mul.rn.f32x2 %0, %1, %2;" : "=l"(d) : "l"(a), "l"(b));
    return d;
}
__device__ __forceinline__ float rcpa(float x) {
    float r; asm("rcp.approx.ftz.f32 %0, %1;" : "=f"(r) : "f"(x)); return r;
}
__device__ __forceinline__ float ex2a(float x) {
    float r; asm("ex2.approx.ftz.f32 %0, %1;" : "=f"(r) : "f"(x)); return r;
}

// Pairwise gelu via Abramowitz-Stegun 7.1.26 erf (abs err <= 1.5e-7).
__device__ __forceinline__ float2 gelu2(float x0, float x1) {
    const float t0 = fabsf(x0) * 0.70710678118654752f;
    const float t1 = fabsf(x1) * 0.70710678118654752f;
    const float k0 = rcpa(fmaf(0.3275911f, t0, 1.0f));
    const float k1 = rcpa(fmaf(0.3275911f, t1, 1.0f));
    const unsigned long long kp = pk2(k0, k1);
    const unsigned long long tp = pk2(t0, t1);
    unsigned long long p = fma2_(pk2(-1.061405429f, -1.061405429f), kp,
                                 pk2(1.453152027f, 1.453152027f));
    p = fma2_(p, kp, pk2(-1.421413741f, -1.421413741f));
    p = fma2_(p, kp, pk2(0.284496736f, 0.284496736f));
    p = fma2_(p, kp, pk2(-0.254829592f, -0.254829592f));
    p = mul2_(p, kp);
    unsigned long long u = mul2_(tp, tp);
    u = mul2_(u, pk2(-1.4426950408889634f, -1.4426950408889634f));
    const float2 uf = upk2(u);
    const unsigned long long ep = pk2(ex2a(uf.x), ex2a(uf.y));
    const float2 ef = upk2(fma2_(p, ep, pk2(1.0f, 1.0f)));
    const float h0 = 0.5f * x0, h1 = 0.5f * x1;
    return make_float2(fmaf(fabsf(h0), ef.x, h0), fmaf(fabsf(h1), ef.y, h1));
}

// ---------------------------------------------------------------------------
// Fill ONLY the 6-wide halo rings of both padded buffers with +BIG.
// ---------------------------------------------------------------------------
__global__ __launch_bounds__(64) void fill_ring_kernel() {
    const int row = blockIdx.x;
    const int plane = blockIdx.y;
    float* base = (blockIdx.z ? g_bufB : g_bufA) + plane * PSZ + row * GP;
    if (row < 6 || row >= 518) {
        for (int c = threadIdx.x; c < GP; c += 64) base[c] = BIGF;
    } else {
        const int tx = threadIdx.x;
        if (tx < 6) base[tx] = BIGF;
        else if (tx < 12) base[512 + tx] = BIGF;
    }
}

// ---------------------------------------------------------------------------
// erode: in (DIN x DIN, halo HOUT+1) -> out (DIN-2 x DIN-2, halo HOUT).
// 512 threads: pair cols (j=2*tx, tx=tid&31? no — 32 col-pairs x 16 row-groups)
// ---------------------------------------------------------------------------
template<int DIN, int HOUT, bool BORDER>
__device__ __forceinline__ void erode_pair(const float* __restrict__ in,
                                           float* __restrict__ out,
                                           int by, int bx, int tx, int ty, int tid) {
    constexpr int DOUT = DIN - 2;
    constexpr int RPT = (DOUT + 15) / 16;
    const int j = 2 * tx;
    const int r0 = ty * RPT;
    int r1 = r0 + RPT; if (r1 > DOUT) r1 = DOUT;
    const int rb = (r0 < DOUT) ? r0 : 0;    // safe base for (possibly idle) setup
    const float* pin = in + rb * DIN + j;
    float2 a0 = *(const float2*)(pin),       a1 = *(const float2*)(pin + 2);
    float2 b0 = *(const float2*)(pin + DIN), b1 = *(const float2*)(pin + DIN + 2);
    const float* nrow = pin + 2 * DIN;
    float* orow = out + rb * DOUT + j;
    bool c0ok = true, c1ok = true;
    if (BORDER) {
        c0ok = (unsigned)(bx + j - HOUT) < 512u;
        c1ok = (unsigned)(bx + j + 1 - HOUT) < 512u;
    }
    for (int i = r0; i < r1; ++i) {
        const float2 c0 = *(const float2*)(nrow), c1 = *(const float2*)(nrow + 2);
        const float v1 = fminf(fminf(a0.y, b0.y), c0.y);
        const float v2 = fminf(fminf(a1.x, b1.x), c1.x);
        float o0 = fminf(v1, fminf(b0.x, b1.x));
        float o1 = fminf(v2, fminf(b0.y, b1.y));
        if (BORDER) {
            const bool rok = (unsigned)(by + i - HOUT) < 512u;
            if (!rok | !c0ok) o0 = BIGF;
            if (!rok | !c1ok) o1 = BIGF;
        }
        *(float2*)orow = make_float2(o0, o1);
        a0 = b0; a1 = b1; b0 = c0; b1 = c1;
        nrow += DIN; orow += DOUT;
    }
    constexpr int EX = (DOUT - 64) * DOUT;
    for (int e = tid; e < EX; e += NT) {
        const int q = e / DOUT, jj = 64 + q, i = e - q * DOUT;
        float v = fminf(fminf(in[i * DIN + jj + 1], in[(i + 1) * DIN + jj + 1]),
                        in[(i + 2) * DIN + jj + 1]);
        v = fminf(v, fminf(in[(i + 1) * DIN + jj], in[(i + 1) * DIN + jj + 2]));
        if (BORDER) {
            const int gr = by + i - HOUT, gc = bx + jj - HOUT;
            if ((unsigned)gr >= 512u || (unsigned)gc >= 512u) v = BIGF;
        }
        out[i * DOUT + jj] = v;
    }
}

// ---------------------------------------------------------------------------
// upd: delta = gelu(Ek - dilate(Ek1)); INIT: sk = delta; else sk += gelu(d - sk*d)
// 512 threads: each thread 4 rows (r0 = ty*4), pair columns.
// ---------------------------------------------------------------------------
template<int DK, int HK, bool BORDER, bool INIT>
__device__ __forceinline__ void upd_pair(const float* __restrict__ ek,
                                         const float* __restrict__ ek1,
                                         float2* sk, int by, int bx, int tx, int ty) {
    constexpr int DK1 = DK - 2, H1 = HK - 1;
    const int j = 2 * tx, r0 = ty * 4;
    bool okL = true, okR = true;
    if (BORDER) {
        okL = (unsigned)(bx + j - 1) < 512u;
        okR = (unsigned)(bx + j + 2) < 512u;
    }
    auto rowpair = [&](int ri, bool rok) -> float2 {
        const float* p = ek1 + ri * DK1 + (j + H1 - 1);
        float v0, v1, v2, v3;
        if constexpr ((H1 & 1) == 1) {
            const float2 u = *(const float2*)(p);
            const float2 w = *(const float2*)(p + 2);
            v0 = u.x; v1 = u.y; v2 = w.x; v3 = w.y;
        } else {
            const float2 u = *(const float2*)(p + 1);
            v0 = p[0]; v1 = u.x; v2 = u.y; v3 = p[3];
        }
        if (BORDER) { if (!okL) v0 = -BIGF; if (!okR) v3 = -BIGF; }
        const float m = fmaxf(v1, v2);
        float2 rm = make_float2(fmaxf(m, v0), fmaxf(m, v3));
        if (BORDER && !rok) { rm.x = -BIGF; rm.y = -BIGF; }
        return rm;
    };
    float2 rma = rowpair(r0 + H1 - 1, !BORDER || ((unsigned)(by + r0 - 1) < 512u));
    float2 rmb = rowpair(r0 + H1, true);
    #pragma unroll
    for (int q = 0; q < 4; ++q) {
        const int r = r0 + q;
        const float2 rmc = rowpair(r + H1 + 1, !BORDER || ((unsigned)(by + r + 1) < 512u));
        const float o0 = fmaxf(fmaxf(rma.x, rmb.x), rmc.x);
        const float o1 = fmaxf(fmaxf(rma.y, rmb.y), rmc.y);
        const float* pc = ek + (r + HK) * DK + (j + HK);
        float e0, e1;
        if constexpr ((HK & 1) == 0) { const float2 u = *(const float2*)pc; e0 = u.x; e1 = u.y; }
        else { e0 = pc[0]; e1 = pc[1]; }
        const float2 d = gelu2(e0 - o0, e1 - o1);
        if (INIT) {
            sk[q] = d;
        } else {
            float s0 = sk[q].x, s1 = sk[q].y;
            const float2 g = gelu2(d.x - s0 * d.x, d.y - s1 * d.y);
            sk[q] = make_float2(s0 + g.x, s1 + g.y);
        }
        rma = rmb; rmb = rmc;
    }
}

__device__ __forceinline__ float warpSum(float v) {
    #pragma unroll
    for (int o = 16; o; o >>= 1) v += __shfl_down_sync(0xffffffffu, v, o);
    return v;
}

// ---------------------------------------------------------------------------
// Fused body (512 threads, 32x16 logical). Stage dims=pitch: 76,74,72,70,68,66.
// ---------------------------------------------------------------------------
template<bool BORDER, bool RED, bool INIT>
__device__ __forceinline__ void fused_body(const float* __restrict__ sp,
                                           const float* __restrict__ raw,
                                           float* __restrict__ dp,
                                           const float* __restrict__ yt,
                                           const float* __restrict__ yp,
                                           float* sX, float* sY, float* s_red,
                                           int plane, int by, int bx, int tid) {
    const int tx = tid & 31, ty = tid >> 5;   // 32 col-pairs x 16 row-groups

    // Load x with halo 6 into sX (pitch 76).
    if (INIT) {
        for (int r = ty; r < 76; r += 16) {
            float* srow = sX + r * 76;
            const int gr = by + r - 6;
            if (!BORDER) {
                const float* grp = raw + gr * W + bx - 6;
                *(float2*)(srow + 2 * tx) = *(const float2*)(grp + 2 * tx);
                if (tx < 6) *(float2*)(srow + 64 + 2 * tx) = *(const float2*)(grp + 64 + 2 * tx);
            } else {
                const bool rok = (unsigned)gr < 512u;
                {
                    const int gc = bx + 2 * tx - 6;
                    float v0 = BIGF, v1 = BIGF;
                    if (rok) {
                        if ((unsigned)gc < 512u) v0 = raw[gr * W + gc];
                        if ((unsigned)(gc + 1) < 512u) v1 = raw[gr * W + gc + 1];
                    }
                    *(float2*)(srow + 2 * tx) = make_float2(v0, v1);
                }
                if (tx < 6) {
                    const int gc = bx + 58 + 2 * tx;
                    float v0 = BIGF, v1 = BIGF;
                    if (rok) {
                        if ((unsigned)gc < 512u) v0 = raw[gr * W + gc];
                        if ((unsigned)(gc + 1) < 512u) v1 = raw[gr * W + gc + 1];
                    }
                    *(float2*)(srow + 64 + 2 * tx) = make_float2(v0, v1);
                }
            }
        }
    } else {
        const float* g0 = sp + (by - 6) * GP + (bx - 6);
        for (int r = ty; r < 76; r += 16) {
            const float2* grp = (const float2*)(g0 + r * GP);
            float2* srow = (float2*)(sX + r * 76);
            srow[tx] = grp[tx];
            if (tx < 6) srow[tx + 32] = grp[tx + 32];
        }
    }
    __syncthreads();

    erode_pair<76, 5, BORDER>(sX, sY, by, bx, tx, ty, tid);   // E1 (74, h5)
    __syncthreads();

    float2 sk[4];
    const int r0 = ty * 4, j = 2 * tx;

    if (INIT) {
        // skel = gelu(X - dilate(E1)); X in sX (76, h6), E1 in sY (74, h5)
        upd_pair<76, 6, BORDER, true>(sX, sY, sk, by, bx, tx, ty);
        __syncthreads();          // before E2 overwrites sX
    }

    erode_pair<74, 4, BORDER>(sY, sX, by, bx, tx, ty, tid);   // E2 (72, h4)
    __syncthreads();

    if (!INIT) {
        const float* gs = &g_skel[plane * PLANE + (by + r0) * W + bx + j];
        #pragma unroll
        for (int q = 0; q < 4; ++q) sk[q] = *(const float2*)(gs + q * W);
    }
    upd_pair<74, 5, BORDER, false>(sY, sX, sk, by, bx, tx, ty);   // step 1
    __syncthreads();
    erode_pair<72, 3, BORDER>(sX, sY, by, bx, tx, ty, tid);   // E3 (70, h3)
    __syncthreads();
    upd_pair<72, 4, BORDER, false>(sX, sY, sk, by, bx, tx, ty);   // step 2
    __syncthreads();
    erode_pair<70, 2, BORDER>(sY, sX, by, bx, tx, ty, tid);   // E4 (68, h2)
    __syncthreads();
    upd_pair<70, 3, BORDER, false>(sY, sX, sk, by, bx, tx, ty);   // step 3
    __syncthreads();
    erode_pair<68, 1, BORDER>(sX, sY, by, bx, tx, ty, tid);   // E5 (66, h1)
    __syncthreads();
    upd_pair<68, 2, BORDER, false>(sX, sY, sk, by, bx, tx, ty);   // step 4

    if (!RED) {
        float* gs = &g_skel[plane * PLANE + (by + r0) * W + bx + j];
        float* gd = dp + (by + r0) * GP + bx + j;
        #pragma unroll
        for (int q = 0; q < 4; ++q) {
            *(float2*)(gs + q * W) = sk[q];
            *(float2*)(gd + q * GP) = *(const float2*)(sX + (r0 + q + 2) * 68 + j + 2);
        }
    } else {
        float a0 = 0.f, a1 = 0.f, a2 = 0.f, a3 = 0.f, a4 = 0.f, a5 = 0.f, a6 = 0.f;
        const int gi0 = (plane & 15) * PLANE + (by + r0) * W + bx + j;
        if (plane < HALF) {
            #pragma unroll
            for (int q = 0; q < 4; ++q) {
                const float2 t = *(const float2*)(yt + gi0 + q * W);
                const float2 p = *(const float2*)(yp + gi0 + q * W);
                const float2 s = sk[q];
                a0 += t.x + t.y;
                a1 += p.x + p.y;
                a2 += t.x * p.x + t.y * p.y;
                a3 += s.x + s.y;
                a4 += s.x * t.x + s.y * t.y;
            }
        } else {
            #pragma unroll
            for (int q = 0; q < 4; ++q) {
                const float2 p = *(const float2*)(yp + gi0 + q * W);
                const float2 s = sk[q];
                a5 += s.x + s.y;
                a6 += s.x * p.x + s.y * p.y;
            }
        }
        float v[7] = {a0, a1, a2, a3, a4, a5, a6};
        const int lane = tid & 31, wrp = tid >> 5;   // 16 warps
        #pragma unroll
        for (int k = 0; k < 7; k++) {
            const float s = warpSum(v[k]);
            if (lane == 0) s_red[wrp * 8 + k] = s;
        }
        __syncthreads();
        if (wrp == 0) {
            const int bid = plane * 64 + (by >> 6) * 8 + (bx >> 6);
            #pragma unroll
            for (int k = 0; k < 7; k++) {
                float s = (lane < 16) ? s_red[lane * 8 + k] : 0.f;
                s = warpSum(s);
                if (lane == 0) g_part[bid * 8 + k] = s;
            }
        }
    }
}

// ---------------------------------------------------------------------------
// Kernel wrappers
// ---------------------------------------------------------------------------
__global__ __launch_bounds__(NT, 3) void fused_init_kernel(const float* __restrict__ yt,
                                                           const float* __restrict__ yp) {
    __shared__ __align__(16) float sX[76 * 76];
    __shared__ __align__(16) float sY[74 * 74];
    const int plane = blockIdx.z;
    const float* raw = ((plane < HALF) ? yp : yt) + (plane & 15) * PLANE;
    const int by = blockIdx.y * 64, bx = blockIdx.x * 64;
    float* dp = g_bufA + plane * PSZ + BOFF;
    const bool border = (blockIdx.x == 0) | (blockIdx.x == 7) | (blockIdx.y == 0) | (blockIdx.y == 7);
    if (border) fused_body<true , false, true>(nullptr, raw, dp, nullptr, nullptr, sX, sY, nullptr,
                                               plane, by, bx, threadIdx.x);
    else        fused_body<false, false, true>(nullptr, raw, dp, nullptr, nullptr, sX, sY, nullptr,
                                               plane, by, bx, threadIdx.x);
}

__global__ __launch_bounds__(NT, 3) void fused_kernel(int readA) {
    __shared__ __align__(16) float sX[76 * 76];
    __shared__ __align__(16) float sY[74 * 74];
    const float* src = readA ? g_bufA : g_bufB;
    float* dst = readA ? g_bufB : g_bufA;
    const int plane = blockIdx.z;
    const int by = blockIdx.y * 64, bx = blockIdx.x * 64;
    const float* sp = src + plane * PSZ + BOFF;
    float* dp = dst + plane * PSZ + BOFF;
    const bool border = (blockIdx.x == 0) | (blockIdx.x == 7) | (blockIdx.y == 0) | (blockIdx.y == 7);
    if (border) fused_body<true , false, false>(sp, nullptr, dp, nullptr, nullptr, sX, sY, nullptr,
                                                plane, by, bx, threadIdx.x);
    else        fused_body<false, false, false>(sp, nullptr, dp, nullptr, nullptr, sX, sY, nullptr,
                                                plane, by, bx, threadIdx.x);
}

__global__ __launch_bounds__(NT, 3) void fused_red_kernel(const float* __restrict__ yt,
                                                          const float* __restrict__ yp,
                                                          int readA) {
    __shared__ __align__(16) float sX[76 * 76];
    __shared__ __align__(16) float sY[74 * 74];
    __shared__ float s_red[128];
    const float* src = readA ? g_bufA : g_bufB;
    float* dst = readA ? g_bufB : g_bufA;
    const int plane = blockIdx.z;
    const int by = blockIdx.y * 64, bx = blockIdx.x * 64;
    const float* sp = src + plane * PSZ + BOFF;
    float* dp = dst + plane * PSZ + BOFF;
    const bool border = (blockIdx.x == 0) | (blockIdx.x == 7) | (blockIdx.y == 0) | (blockIdx.y == 7);
    if (border) fused_body<true , true, false>(sp, nullptr, dp, yt, yp, sX, sY, s_red,
                                               plane, by, bx, threadIdx.x);
    else        fused_body<false, true, false>(sp, nullptr, dp, yt, yp, sX, sY, s_red,
                                               plane, by, bx, threadIdx.x);
}

// ---------------------------------------------------------------------------
// Final: sum 2048 partials, compute loss scalar
// ---------------------------------------------------------------------------
__global__ __launch_bounds__(256) void final_kernel(float* __restrict__ out) {
    float a[7] = {0.f, 0.f, 0.f, 0.f, 0.f, 0.f, 0.f};
    for (int b = threadIdx.x; b < NBLOCKS; b += 256) {
        #pragma unroll
        for (int j = 0; j < 7; j++) a[j] += g_part[b * 8 + j];
    }
    __shared__ float shm[8][8];
    const int lane = threadIdx.x & 31, wrp = threadIdx.x >> 5;
    #pragma unroll
    for (int j = 0; j < 7; j++) {
        const float v = warpSum(a[j]);
        if (lane == 0) shm[wrp][j] = v;
    }
    __syncthreads();
    if (wrp == 0) {
        float res[7];
        #pragma unroll
        for (int j = 0; j < 7; j++) {
            float v = (lane < 8) ? shm[lane][j] : 0.f;
            res[j] = warpSum(v);
        }
        if (lane == 0) {
            const float S_t = res[0], S_p = res[1], S_tp = res[2];
            const float S_sp = res[3], S_spt = res[4];
            const float S_st = res[5], S_stp = res[6];
            const float dice  = 1.0f - (2.0f * S_tp + 1.0f) / (S_t + S_p + 1.0f);
            const float tprec = (S_spt + 1.0f) / (S_sp + 1.0f);
            const float tsens = (S_stp + 1.0f) / (S_st + 1.0f);
            const float cl    = 1.0f - 2.0f * (tprec * tsens) / (tprec + tsens);
            out[0] = 0.7f * dice + 0.3f * cl;
        }
    }
}

// ---------------------------------------------------------------------------
extern "C" void kernel_launch(void* const* d_in, const int* in_sizes, int n_in,
                              void* d_out, int out_size) {
    const float* y_true = (const float*)d_in[0];
    const float* y_pred = (const float*)d_in[1];

    dim3 grid(8, 8, NPLANES);
    dim3 blk(NT);

    fill_ring_kernel<<<dim3(GR, NPLANES, 2), 64>>>();
    fused_init_kernel<<<grid, blk>>>(y_true, y_pred);    // init + steps 1-4  -> A
    fused_kernel<<<grid, blk>>>(1);                      // steps 5-8   A -> B
    fused_kernel<<<grid, blk>>>(0);                      // steps 9-12  B -> A
    fused_kernel<<<grid, blk>>>(1);                      // steps 13-16 A -> B
    fused_red_kernel<<<grid, blk>>>(y_true, y_pred, 0);  // steps 17-20 + sums (reads B)
    final_kernel<<<1, 256>>>((float*)d_out);
}

// round 16
// speedup vs baseline: 1.1026x; 1.0456x over previous
#include <cuda_runtime.h>

#define W 512
#define PLANE (512*512)
#define NPLANES 32
#define HALF 16
#define TOTAL (NPLANES*PLANE)
#define GP 524                  // padded pitch (6 + 512 + 6)
#define GR 524
#define PSZ (GP*GR)
#define BOFF (6*GP + 6)         // offset of pixel (0,0) in a padded plane
#define NT 256
#define NBLOCKS 2048
#define BIGF 1e30f

// Scratch (device globals; no allocation allowed)
__device__ __align__(16) float g_bufA[NPLANES * PSZ];
__device__ __align__(16) float g_bufB[NPLANES * PSZ];
__device__ __align__(16) float g_skel[TOTAL];
__device__ float g_part[NBLOCKS * 8];

// ---------------------------------------------------------------------------
// Packed f32x2 helpers (PTX-only packed fp32; sm_100+)
// ---------------------------------------------------------------------------
__device__ __forceinline__ unsigned long long pk2(float a, float b) {
    unsigned long long r;
    asm("mov.b64 %0, {%1, %2};" : "=l"(r) : "f"(a), "f"(b));
    return r;
}
__device__ __forceinline__ float2 upk2(unsigned long long v) {
    float a, b;
    asm("mov.b64 {%0, %1}, %2;" : "=f"(a), "=f"(b) : "l"(v));
    return make_float2(a, b);
}
__device__ __forceinline__ unsigned long long fma2_(unsigned long long a,
                                                    unsigned long long b,
                                                    unsigned long long c) {
    unsigned long long d;
    asm("fma.rn.f32x2 %0, %1, %2, %3;" : "=l"(d) : "l"(a), "l"(b), "l"(c));
    return d;
}
__device__ __forceinline__ unsigned long long mul2_(unsigned long long a,
                                                    unsigned long long b) {
    unsigned long long d;
    asm("mul.rn.f32x2 %0, %1, %2;" : "=l"(d) : "l"(a), "l"(b));
    return d;
}
__device__ __forceinline__ float rcpa(float x) {
    float r; asm("rcp.approx.ftz.f32 %0, %1;" : "=f"(r) : "f"(x)); return r;
}
__device__ __forceinline__ float ex2a(float x) {
    float r; asm("ex2.approx.ftz.f32 %0, %1;" : "=f"(r) : "f"(x)); return r;
}

// Pairwise gelu via Abramowitz-Stegun 7.1.26 erf (abs err <= 1.5e-7).
__device__ __forceinline__ float2 gelu2(float x0, float x1) {
    const float t0 = fabsf(x0) * 0.70710678118654752f;
    const float t1 = fabsf(x1) * 0.70710678118654752f;
    const float k0 = rcpa(fmaf(0.3275911f, t0, 1.0f));
    const float k1 = rcpa(fmaf(0.3275911f, t1, 1.0f));
    const unsigned long long kp = pk2(k0, k1);
    const unsigned long long tp = pk2(t0, t1);
    unsigned long long p = fma2_(pk2(-1.061405429f, -1.061405429f), kp,
                                 pk2(1.453152027f, 1.453152027f));
    p = fma2_(p, kp, pk2(-1.421413741f, -1.421413741f));
    p = fma2_(p, kp, pk2(0.284496736f, 0.284496736f));
    p = fma2_(p, kp, pk2(-0.254829592f, -0.254829592f));
    p = mul2_(p, kp);
    unsigned long long u = mul2_(tp, tp);
    u = mul2_(u, pk2(-1.4426950408889634f, -1.4426950408889634f));
    const float2 uf = upk2(u);
    const unsigned long long ep = pk2(ex2a(uf.x), ex2a(uf.y));
    const float2 ef = upk2(fma2_(p, ep, pk2(1.0f, 1.0f)));
    const float h0 = 0.5f * x0, h1 = 0.5f * x1;
    return make_float2(fmaf(fabsf(h0), ef.x, h0), fmaf(fabsf(h1), ef.y, h1));
}

// ---------------------------------------------------------------------------
// Fill ONLY the 6-wide halo rings of both padded buffers with +BIG.
// ---------------------------------------------------------------------------
__global__ __launch_bounds__(64) void fill_ring_kernel() {
    const int row = blockIdx.x;
    const int plane = blockIdx.y;
    float* base = (blockIdx.z ? g_bufB : g_bufA) + plane * PSZ + row * GP;
    if (row < 6 || row >= 518) {
        for (int c = threadIdx.x; c < GP; c += 64) base[c] = BIGF;
    } else {
        const int tx = threadIdx.x;
        if (tx < 6) base[tx] = BIGF;
        else if (tx < 12) base[512 + tx] = BIGF;
    }
}

// ---------------------------------------------------------------------------
// erode: in (DIN x DIN, halo HOUT+1) -> out (DIN-2 x DIN-2, halo HOUT).
// 256 threads: 32 col-pairs x 8 row-groups; rolling 3-row float2 window.
// ---------------------------------------------------------------------------
template<int DIN, int HOUT, bool BORDER>
__device__ __forceinline__ void erode_pair(const float* __restrict__ in,
                                           float* __restrict__ out,
                                           int by, int bx, int tx, int ty, int tid) {
    constexpr int DOUT = DIN - 2;
    constexpr int RPT = (DOUT + 7) / 8;
    const int j = 2 * tx;
    const int r0 = ty * RPT;
    int r1 = r0 + RPT; if (r1 > DOUT) r1 = DOUT;
    const float* pin = in + r0 * DIN + j;
    float2 a0 = *(const float2*)(pin),       a1 = *(const float2*)(pin + 2);
    float2 b0 = *(const float2*)(pin + DIN), b1 = *(const float2*)(pin + DIN + 2);
    const float* nrow = pin + 2 * DIN;
    float* orow = out + r0 * DOUT + j;
    bool c0ok = true, c1ok = true;
    if (BORDER) {
        c0ok = (unsigned)(bx + j - HOUT) < 512u;
        c1ok = (unsigned)(bx + j + 1 - HOUT) < 512u;
    }
    #pragma unroll 2
    for (int i = r0; i < r1; ++i) {
        const float2 c0 = *(const float2*)(nrow), c1 = *(const float2*)(nrow + 2);
        const float v1 = fminf(fminf(a0.y, b0.y), c0.y);
        const float v2 = fminf(fminf(a1.x, b1.x), c1.x);
        float o0 = fminf(v1, fminf(b0.x, b1.x));
        float o1 = fminf(v2, fminf(b0.y, b1.y));
        if (BORDER) {
            const bool rok = (unsigned)(by + i - HOUT) < 512u;
            if (!rok | !c0ok) o0 = BIGF;
            if (!rok | !c1ok) o1 = BIGF;
        }
        *(float2*)orow = make_float2(o0, o1);
        a0 = b0; a1 = b1; b0 = c0; b1 = c1;
        nrow += DIN; orow += DOUT;
    }
    constexpr int EX = (DOUT - 64) * DOUT;
    #pragma unroll 2
    for (int e = tid; e < EX; e += NT) {
        const int q = e / DOUT, jj = 64 + q, i = e - q * DOUT;
        float v = fminf(fminf(in[i * DIN + jj + 1], in[(i + 1) * DIN + jj + 1]),
                        in[(i + 2) * DIN + jj + 1]);
        v = fminf(v, fminf(in[(i + 1) * DIN + jj], in[(i + 1) * DIN + jj + 2]));
        if (BORDER) {
            const int gr = by + i - HOUT, gc = bx + jj - HOUT;
            if ((unsigned)gr >= 512u || (unsigned)gc >= 512u) v = BIGF;
        }
        out[i * DOUT + jj] = v;
    }
}

// ---------------------------------------------------------------------------
// upd: delta = gelu(Ek - dilate(Ek1)); INIT: sk = delta; else sk += gelu(d - sk*d)
// ---------------------------------------------------------------------------
template<int DK, int HK, bool BORDER, bool INIT>
__device__ __forceinline__ void upd_pair(const float* __restrict__ ek,
                                         const float* __restrict__ ek1,
                                         float2* sk, int by, int bx, int tx, int ty) {
    constexpr int DK1 = DK - 2, H1 = HK - 1;
    const int j = 2 * tx, r0 = ty * 8;
    bool okL = true, okR = true;
    if (BORDER) {
        okL = (unsigned)(bx + j - 1) < 512u;
        okR = (unsigned)(bx + j + 2) < 512u;
    }
    auto rowpair = [&](int ri, bool rok) -> float2 {
        const float* p = ek1 + ri * DK1 + (j + H1 - 1);
        float v0, v1, v2, v3;
        if constexpr ((H1 & 1) == 1) {
            const float2 u = *(const float2*)(p);
            const float2 w = *(const float2*)(p + 2);
            v0 = u.x; v1 = u.y; v2 = w.x; v3 = w.y;
        } else {
            const float2 u = *(const float2*)(p + 1);
            v0 = p[0]; v1 = u.x; v2 = u.y; v3 = p[3];
        }
        if (BORDER) { if (!okL) v0 = -BIGF; if (!okR) v3 = -BIGF; }
        const float m = fmaxf(v1, v2);
        float2 rm = make_float2(fmaxf(m, v0), fmaxf(m, v3));
        if (BORDER && !rok) { rm.x = -BIGF; rm.y = -BIGF; }
        return rm;
    };
    float2 rma = rowpair(r0 + H1 - 1, !BORDER || ((unsigned)(by + r0 - 1) < 512u));
    float2 rmb = rowpair(r0 + H1, true);
    #pragma unroll
    for (int q = 0; q < 8; ++q) {
        const int r = r0 + q;
        const float2 rmc = rowpair(r + H1 + 1, !BORDER || ((unsigned)(by + r + 1) < 512u));
        const float o0 = fmaxf(fmaxf(rma.x, rmb.x), rmc.x);
        const float o1 = fmaxf(fmaxf(rma.y, rmb.y), rmc.y);
        const float* pc = ek + (r + HK) * DK + (j + HK);
        float e0, e1;
        if constexpr ((HK & 1) == 0) { const float2 u = *(const float2*)pc; e0 = u.x; e1 = u.y; }
        else { e0 = pc[0]; e1 = pc[1]; }
        const float2 d = gelu2(e0 - o0, e1 - o1);
        if (INIT) {
            sk[q] = d;
        } else {
            float s0 = sk[q].x, s1 = sk[q].y;
            const float2 g = gelu2(d.x - s0 * d.x, d.y - s1 * d.y);
            sk[q] = make_float2(s0 + g.x, s1 + g.y);
        }
        rma = rmb; rmb = rmc;
    }
}

__device__ __forceinline__ float warpSum(float v) {
    #pragma unroll
    for (int o = 16; o; o >>= 1) v += __shfl_down_sync(0xffffffffu, v, o);
    return v;
}

// ---------------------------------------------------------------------------
// Fused body (256 threads, 32x8). Stage dims=pitch: 76,74,72,70,68,66.
// ---------------------------------------------------------------------------
template<bool BORDER, bool RED, bool INIT>
__device__ __forceinline__ void fused_body(const float* __restrict__ sp,
                                           const float* __restrict__ raw,
                                           float* __restrict__ dp,
                                           const float* __restrict__ yt,
                                           const float* __restrict__ yp,
                                           float* sX, float* sY, float* s_red,
                                           int plane, int by, int bx, int tid) {
    const int tx = tid & 31, ty = tid >> 5;

    // Load x with halo 6 into sX (pitch 76).
    if (INIT) {
        for (int r = ty; r < 76; r += 8) {
            float* srow = sX + r * 76;
            const int gr = by + r - 6;
            if (!BORDER) {
                const float* grp = raw + gr * W + bx - 6;
                *(float2*)(srow + 2 * tx) = *(const float2*)(grp + 2 * tx);
                if (tx < 6) *(float2*)(srow + 64 + 2 * tx) = *(const float2*)(grp + 64 + 2 * tx);
            } else {
                const bool rok = (unsigned)gr < 512u;
                {
                    const int gc = bx + 2 * tx - 6;
                    float v0 = BIGF, v1 = BIGF;
                    if (rok) {
                        if ((unsigned)gc < 512u) v0 = raw[gr * W + gc];
                        if ((unsigned)(gc + 1) < 512u) v1 = raw[gr * W + gc + 1];
                    }
                    *(float2*)(srow + 2 * tx) = make_float2(v0, v1);
                }
                if (tx < 6) {
                    const int gc = bx + 58 + 2 * tx;
                    float v0 = BIGF, v1 = BIGF;
                    if (rok) {
                        if ((unsigned)gc < 512u) v0 = raw[gr * W + gc];
                        if ((unsigned)(gc + 1) < 512u) v1 = raw[gr * W + gc + 1];
                    }
                    *(float2*)(srow + 64 + 2 * tx) = make_float2(v0, v1);
                }
            }
        }
    } else {
        const float* g0 = sp + (by - 6) * GP + (bx - 6);
        for (int r = ty; r < 76; r += 8) {
            const float2* grp = (const float2*)(g0 + r * GP);
            float2* srow = (float2*)(sX + r * 76);
            srow[tx] = grp[tx];
            if (tx < 6) srow[tx + 32] = grp[tx + 32];
        }
    }

    float2 sk[8];
    const int r0 = ty * 8, j = 2 * tx;

    // Prefetch skel early (non-INIT): independent of E1/E2; hides LDG latency.
    if (!INIT) {
        const float* gs = &g_skel[plane * PLANE + (by + r0) * W + bx + j];
        #pragma unroll
        for (int q = 0; q < 8; ++q) sk[q] = *(const float2*)(gs + q * W);
    }
    __syncthreads();

    erode_pair<76, 5, BORDER>(sX, sY, by, bx, tx, ty, tid);   // E1 (74, h5)
    __syncthreads();

    if (INIT) {
        // skel = gelu(X - dilate(E1)); X in sX (76, h6), E1 in sY (74, h5)
        upd_pair<76, 6, BORDER, true>(sX, sY, sk, by, bx, tx, ty);
        __syncthreads();          // before E2 overwrites sX
    }

    erode_pair<74, 4, BORDER>(sY, sX, by, bx, tx, ty, tid);   // E2 (72, h4)
    __syncthreads();

    upd_pair<74, 5, BORDER, false>(sY, sX, sk, by, bx, tx, ty);   // step 1
    __syncthreads();
    erode_pair<72, 3, BORDER>(sX, sY, by, bx, tx, ty, tid);   // E3 (70, h3)
    __syncthreads();
    upd_pair<72, 4, BORDER, false>(sX, sY, sk, by, bx, tx, ty);   // step 2
    __syncthreads();
    erode_pair<70, 2, BORDER>(sY, sX, by, bx, tx, ty, tid);   // E4 (68, h2)
    __syncthreads();
    upd_pair<70, 3, BORDER, false>(sY, sX, sk, by, bx, tx, ty);   // step 3
    __syncthreads();
    erode_pair<68, 1, BORDER>(sX, sY, by, bx, tx, ty, tid);   // E5 (66, h1)
    __syncthreads();
    upd_pair<68, 2, BORDER, false>(sX, sY, sk, by, bx, tx, ty);   // step 4

    if (!RED) {
        float* gs = &g_skel[plane * PLANE + (by + r0) * W + bx + j];
        float* gd = dp + (by + r0) * GP + bx + j;
        #pragma unroll
        for (int q = 0; q < 8; ++q) {
            *(float2*)(gs + q * W) = sk[q];
            *(float2*)(gd + q * GP) = *(const float2*)(sX + (r0 + q + 2) * 68 + j + 2);
        }
    } else {
        float a0 = 0.f, a1 = 0.f, a2 = 0.f, a3 = 0.f, a4 = 0.f, a5 = 0.f, a6 = 0.f;
        const int gi0 = (plane & 15) * PLANE + (by + r0) * W + bx + j;
        if (plane < HALF) {
            #pragma unroll
            for (int q = 0; q < 8; ++q) {
                const float2 t = *(const float2*)(yt + gi0 + q * W);
                const float2 p = *(const float2*)(yp + gi0 + q * W);
                const float2 s = sk[q];
                a0 += t.x + t.y;
                a1 += p.x + p.y;
                a2 += t.x * p.x + t.y * p.y;
                a3 += s.x + s.y;
                a4 += s.x * t.x + s.y * t.y;
            }
        } else {
            #pragma unroll
            for (int q = 0; q < 8; ++q) {
                const float2 p = *(const float2*)(yp + gi0 + q * W);
                const float2 s = sk[q];
                a5 += s.x + s.y;
                a6 += s.x * p.x + s.y * p.y;
            }
        }
        float v[7] = {a0, a1, a2, a3, a4, a5, a6};
        const int lane = tid & 31, wrp = tid >> 5;
        #pragma unroll
        for (int k = 0; k < 7; k++) {
            const float s = warpSum(v[k]);
            if (lane == 0) s_red[wrp * 8 + k] = s;
        }
        __syncthreads();
        if (wrp == 0) {
            const int bid = plane * 64 + (by >> 6) * 8 + (bx >> 6);
            #pragma unroll
            for (int k = 0; k < 7; k++) {
                float s = (lane < 8) ? s_red[lane * 8 + k] : 0.f;
                s = warpSum(s);
                if (lane == 0) g_part[bid * 8 + k] = s;
            }
        }
    }
}

// ---------------------------------------------------------------------------
// Kernel wrappers
// ---------------------------------------------------------------------------
__global__ __launch_bounds__(NT, 5) void fused_init_kernel(const float* __restrict__ yt,
                                                           const float* __restrict__ yp) {
    __shared__ __align__(16) float sX[76 * 76];
    __shared__ __align__(16) float sY[74 * 74];
    const int plane = blockIdx.z;
    const float* raw = ((plane < HALF) ? yp : yt) + (plane & 15) * PLANE;
    const int by = blockIdx.y * 64, bx = blockIdx.x * 64;
    float* dp = g_bufA + plane * PSZ + BOFF;
    const bool border = (blockIdx.x == 0) | (blockIdx.x == 7) | (blockIdx.y == 0) | (blockIdx.y == 7);
    if (border) fused_body<true , false, true>(nullptr, raw, dp, nullptr, nullptr, sX, sY, nullptr,
                                               plane, by, bx, threadIdx.x);
    else        fused_body<false, false, true>(nullptr, raw, dp, nullptr, nullptr, sX, sY, nullptr,
                                               plane, by, bx, threadIdx.x);
}

__global__ __launch_bounds__(NT, 5) void fused_kernel(int readA) {
    __shared__ __align__(16) float sX[76 * 76];
    __shared__ __align__(16) float sY[74 * 74];
    const float* src = readA ? g_bufA : g_bufB;
    float* dst = readA ? g_bufB : g_bufA;
    const int plane = blockIdx.z;
    const int by = blockIdx.y * 64, bx = blockIdx.x * 64;
    const float* sp = src + plane * PSZ + BOFF;
    float* dp = dst + plane * PSZ + BOFF;
    const bool border = (blockIdx.x == 0) | (blockIdx.x == 7) | (blockIdx.y == 0) | (blockIdx.y == 7);
    if (border) fused_body<true , false, false>(sp, nullptr, dp, nullptr, nullptr, sX, sY, nullptr,
                                                plane, by, bx, threadIdx.x);
    else        fused_body<false, false, false>(sp, nullptr, dp, nullptr, nullptr, sX, sY, nullptr,
                                                plane, by, bx, threadIdx.x);
}

__global__ __launch_bounds__(NT, 5) void fused_red_kernel(const float* __restrict__ yt,
                                                          const float* __restrict__ yp,
                                                          int readA) {
    __shared__ __align__(16) float sX[76 * 76];
    __shared__ __align__(16) float sY[74 * 74];
    __shared__ float s_red[64];
    const float* src = readA ? g_bufA : g_bufB;
    float* dst = readA ? g_bufB : g_bufA;
    const int plane = blockIdx.z;
    const int by = blockIdx.y * 64, bx = blockIdx.x * 64;
    const float* sp = src + plane * PSZ + BOFF;
    float* dp = dst + plane * PSZ + BOFF;
    const bool border = (blockIdx.x == 0) | (blockIdx.x == 7) | (blockIdx.y == 0) | (blockIdx.y == 7);
    if (border) fused_body<true , true, false>(sp, nullptr, dp, yt, yp, sX, sY, s_red,
                                               plane, by, bx, threadIdx.x);
    else        fused_body<false, true, false>(sp, nullptr, dp, yt, yp, sX, sY, s_red,
                                               plane, by, bx, threadIdx.x);
}

// ---------------------------------------------------------------------------
// Final: sum 2048 partials, compute loss scalar
// ---------------------------------------------------------------------------
__global__ __launch_bounds__(256) void final_kernel(float* __restrict__ out) {
    float a[7] = {0.f, 0.f, 0.f, 0.f, 0.f, 0.f, 0.f};
    for (int b = threadIdx.x; b < NBLOCKS; b += 256) {
        #pragma unroll
        for (int j = 0; j < 7; j++) a[j] += g_part[b * 8 + j];
    }
    __shared__ float shm[8][8];
    const int lane = threadIdx.x & 31, wrp = threadIdx.x >> 5;
    #pragma unroll
    for (int j = 0; j < 7; j++) {
        const float v = warpSum(a[j]);
        if (lane == 0) shm[wrp][j] = v;
    }
    __syncthreads();
    if (wrp == 0) {
        float res[7];
        #pragma unroll
        for (int j = 0; j < 7; j++) {
            float v = (lane < 8) ? shm[lane][j] : 0.f;
            res[j] = warpSum(v);
        }
        if (lane == 0) {
            const float S_t = res[0], S_p = res[1], S_tp = res[2];
            const float S_sp = res[3], S_spt = res[4];
            const float S_st = res[5], S_stp = res[6];
            const float dice  = 1.0f - (2.0f * S_tp + 1.0f) / (S_t + S_p + 1.0f);
            const float tprec = (S_spt + 1.0f) / (S_sp + 1.0f);
            const float tsens = (S_stp + 1.0f) / (S_st + 1.0f);
            const float cl    = 1.0f - 2.0f * (tprec * tsens) / (tprec + tsens);
            out[0] = 0.7f * dice + 0.3f * cl;
        }
    }
}

// ---------------------------------------------------------------------------
extern "C" void kernel_launch(void* const* d_in, const int* in_sizes, int n_in,
                              void* d_out, int out_size) {
    const float* y_true = (const float*)d_in[0];
    const float* y_pred = (const float*)d_in[1];

    dim3 grid(8, 8, NPLANES);
    dim3 blk(NT);

    fill_ring_kernel<<<dim3(GR, NPLANES, 2), 64>>>();
    fused_init_kernel<<<grid, blk>>>(y_true, y_pred);    // init + steps 1-4  -> A
    fused_kernel<<<grid, blk>>>(1);                      // steps 5-8   A -> B
    fused_kernel<<<grid, blk>>>(0);                      // steps 9-12  B -> A
    fused_kernel<<<grid, blk>>>(1);                      // steps 13-16 A -> B
    fused_red_kernel<<<grid, blk>>>(y_true, y_pred, 0);  // steps 17-20 + sums (reads B)
    final_kernel<<<1, 256>>>((float*)d_out);
}

// round 17
// speedup vs baseline: 1.1679x; 1.0592x over previous
#include <cuda_runtime.h>

#define W 512
#define PLANE (512*512)
#define NPLANES 32
#define HALF 16
#define TOTAL (NPLANES*PLANE)
#define GP 524                  // padded pitch (6 + 512 + 6)
#define GR 524
#define PSZ (GP*GR)
#define BOFF (6*GP + 6)         // offset of pixel (0,0) in a padded plane
#define NT 256
#define NBLOCKS 2048
#define BIGF 1e30f

// Scratch (device globals; no allocation allowed)
__device__ __align__(16) float g_bufA[NPLANES * PSZ];
__device__ __align__(16) float g_bufB[NPLANES * PSZ];
__device__ __align__(16) float g_skel[TOTAL];
__device__ float g_part[NBLOCKS * 8];

// ---------------------------------------------------------------------------
// Packed f32x2 helpers (PTX-only packed fp32; sm_100+)
// ---------------------------------------------------------------------------
__device__ __forceinline__ unsigned long long pk2(float a, float b) {
    unsigned long long r;
    asm("mov.b64 %0, {%1, %2};" : "=l"(r) : "f"(a), "f"(b));
    return r;
}
__device__ __forceinline__ float2 upk2(unsigned long long v) {
    float a, b;
    asm("mov.b64 {%0, %1}, %2;" : "=f"(a), "=f"(b) : "l"(v));
    return make_float2(a, b);
}
__device__ __forceinline__ unsigned long long fma2_(unsigned long long a,
                                                    unsigned long long b,
                                                    unsigned long long c) {
    unsigned long long d;
    asm("fma.rn.f32x2 %0, %1, %2, %3;" : "=l"(d) : "l"(a), "l"(b), "l"(c));
    return d;
}
__device__ __forceinline__ unsigned long long mul2_(unsigned long long a,
                                                    unsigned long long b) {
    unsigned long long d;
    asm("mul.rn.f32x2 %0, %1, %2;" : "=l"(d) : "l"(a), "l"(b));
    return d;
}
__device__ __forceinline__ float rcpa(float x) {
    float r; asm("rcp.approx.ftz.f32 %0, %1;" : "=f"(r) : "f"(x)); return r;
}
__device__ __forceinline__ float ex2a(float x) {
    float r; asm("ex2.approx.ftz.f32 %0, %1;" : "=f"(r) : "f"(x)); return r;
}

// Pairwise gelu via Abramowitz-Stegun 7.1.26 erf (abs err <= 1.5e-7).
__device__ __forceinline__ float2 gelu2(float x0, float x1) {
    const float t0 = fabsf(x0) * 0.70710678118654752f;
    const float t1 = fabsf(x1) * 0.70710678118654752f;
    const float k0 = rcpa(fmaf(0.3275911f, t0, 1.0f));
    const float k1 = rcpa(fmaf(0.3275911f, t1, 1.0f));
    const unsigned long long kp = pk2(k0, k1);
    const unsigned long long tp = pk2(t0, t1);
    unsigned long long p = fma2_(pk2(-1.061405429f, -1.061405429f), kp,
                                 pk2(1.453152027f, 1.453152027f));
    p = fma2_(p, kp, pk2(-1.421413741f, -1.421413741f));
    p = fma2_(p, kp, pk2(0.284496736f, 0.284496736f));
    p = fma2_(p, kp, pk2(-0.254829592f, -0.254829592f));
    p = mul2_(p, kp);
    unsigned long long u = mul2_(tp, tp);
    u = mul2_(u, pk2(-1.4426950408889634f, -1.4426950408889634f));
    const float2 uf = upk2(u);
    const unsigned long long ep = pk2(ex2a(uf.x), ex2a(uf.y));
    const float2 ef = upk2(fma2_(p, ep, pk2(1.0f, 1.0f)));
    const float h0 = 0.5f * x0, h1 = 0.5f * x1;
    return make_float2(fmaf(fabsf(h0), ef.x, h0), fmaf(fabsf(h1), ef.y, h1));
}

// ---------------------------------------------------------------------------
// Fill ONLY the 6-wide halo rings of both padded buffers with +BIG.
// ---------------------------------------------------------------------------
__global__ __launch_bounds__(64) void fill_ring_kernel() {
    const int row = blockIdx.x;
    const int plane = blockIdx.y;
    float* base = (blockIdx.z ? g_bufB : g_bufA) + plane * PSZ + row * GP;
    if (row < 6 || row >= 518) {
        for (int c = threadIdx.x; c < GP; c += 64) base[c] = BIGF;
    } else {
        const int tx = threadIdx.x;
        if (tx < 6) base[tx] = BIGF;
        else if (tx < 12) base[512 + tx] = BIGF;
    }
}

// ---------------------------------------------------------------------------
// erode: in (DIN x DIN, halo HOUT+1) -> out (DIN-2 x DIN-2, halo HOUT).
// ---------------------------------------------------------------------------
template<int DIN, int HOUT, bool BORDER>
__device__ __forceinline__ void erode_pair(const float* __restrict__ in,
                                           float* __restrict__ out,
                                           int by, int bx, int tx, int ty, int tid) {
    constexpr int DOUT = DIN - 2;
    constexpr int RPT = (DOUT + 7) / 8;
    const int j = 2 * tx;
    const int r0 = ty * RPT;
    int r1 = r0 + RPT; if (r1 > DOUT) r1 = DOUT;
    const float* pin = in + r0 * DIN + j;
    float2 a0 = *(const float2*)(pin),       a1 = *(const float2*)(pin + 2);
    float2 b0 = *(const float2*)(pin + DIN), b1 = *(const float2*)(pin + DIN + 2);
    const float* nrow = pin + 2 * DIN;
    float* orow = out + r0 * DOUT + j;
    bool c0ok = true, c1ok = true;
    if (BORDER) {
        c0ok = (unsigned)(bx + j - HOUT) < 512u;
        c1ok = (unsigned)(bx + j + 1 - HOUT) < 512u;
    }
    for (int i = r0; i < r1; ++i) {
        const float2 c0 = *(const float2*)(nrow), c1 = *(const float2*)(nrow + 2);
        const float v1 = fminf(fminf(a0.y, b0.y), c0.y);
        const float v2 = fminf(fminf(a1.x, b1.x), c1.x);
        float o0 = fminf(v1, fminf(b0.x, b1.x));
        float o1 = fminf(v2, fminf(b0.y, b1.y));
        if (BORDER) {
            const bool rok = (unsigned)(by + i - HOUT) < 512u;
            if (!rok | !c0ok) o0 = BIGF;
            if (!rok | !c1ok) o1 = BIGF;
        }
        *(float2*)orow = make_float2(o0, o1);
        a0 = b0; a1 = b1; b0 = c0; b1 = c1;
        nrow += DIN; orow += DOUT;
    }
    constexpr int EX = (DOUT - 64) * DOUT;
    for (int e = tid; e < EX; e += NT) {
        const int q = e / DOUT, jj = 64 + q, i = e - q * DOUT;
        float v = fminf(fminf(in[i * DIN + jj + 1], in[(i + 1) * DIN + jj + 1]),
                        in[(i + 2) * DIN + jj + 1]);
        v = fminf(v, fminf(in[(i + 1) * DIN + jj], in[(i + 1) * DIN + jj + 2]));
        if (BORDER) {
            const int gr = by + i - HOUT, gc = bx + jj - HOUT;
            if ((unsigned)gr >= 512u || (unsigned)gc >= 512u) v = BIGF;
        }
        out[i * DOUT + jj] = v;
    }
}

// ---------------------------------------------------------------------------
// upd: delta = gelu(Ek - dilate(Ek1)); INIT: sk = delta; else sk += gelu(d - sk*d)
// ---------------------------------------------------------------------------
template<int DK, int HK, bool BORDER, bool INIT>
__device__ __forceinline__ void upd_pair(const float* __restrict__ ek,
                                         const float* __restrict__ ek1,
                                         float2* sk, int by, int bx, int tx, int ty) {
    constexpr int DK1 = DK - 2, H1 = HK - 1;
    const int j = 2 * tx, r0 = ty * 8;
    bool okL = true, okR = true;
    if (BORDER) {
        okL = (unsigned)(bx + j - 1) < 512u;
        okR = (unsigned)(bx + j + 2) < 512u;
    }
    auto rowpair = [&](int ri, bool rok) -> float2 {
        const float* p = ek1 + ri * DK1 + (j + H1 - 1);
        float v0, v1, v2, v3;
        if constexpr ((H1 & 1) == 1) {
            const float2 u = *(const float2*)(p);
            const float2 w = *(const float2*)(p + 2);
            v0 = u.x; v1 = u.y; v2 = w.x; v3 = w.y;
        } else {
            const float2 u = *(const float2*)(p + 1);
            v0 = p[0]; v1 = u.x; v2 = u.y; v3 = p[3];
        }
        if (BORDER) { if (!okL) v0 = -BIGF; if (!okR) v3 = -BIGF; }
        const float m = fmaxf(v1, v2);
        float2 rm = make_float2(fmaxf(m, v0), fmaxf(m, v3));
        if (BORDER && !rok) { rm.x = -BIGF; rm.y = -BIGF; }
        return rm;
    };
    float2 rma = rowpair(r0 + H1 - 1, !BORDER || ((unsigned)(by + r0 - 1) < 512u));
    float2 rmb = rowpair(r0 + H1, true);
    #pragma unroll
    for (int q = 0; q < 8; ++q) {
        const int r = r0 + q;
        const float2 rmc = rowpair(r + H1 + 1, !BORDER || ((unsigned)(by + r + 1) < 512u));
        const float o0 = fmaxf(fmaxf(rma.x, rmb.x), rmc.x);
        const float o1 = fmaxf(fmaxf(rma.y, rmb.y), rmc.y);
        const float* pc = ek + (r + HK) * DK + (j + HK);
        float e0, e1;
        if constexpr ((HK & 1) == 0) { const float2 u = *(const float2*)pc; e0 = u.x; e1 = u.y; }
        else { e0 = pc[0]; e1 = pc[1]; }
        const float2 d = gelu2(e0 - o0, e1 - o1);
        if (INIT) {
            sk[q] = d;
        } else {
            float s0 = sk[q].x, s1 = sk[q].y;
            const float2 g = gelu2(d.x - s0 * d.x, d.y - s1 * d.y);
            sk[q] = make_float2(s0 + g.x, s1 + g.y);
        }
        rma = rmb; rmb = rmc;
    }
}

__device__ __forceinline__ float warpSum(float v) {
    #pragma unroll
    for (int o = 16; o; o >>= 1) v += __shfl_down_sync(0xffffffffu, v, o);
    return v;
}

// ---------------------------------------------------------------------------
// Fused body. The inter-kernel image is ONE ERODE AHEAD (E1-level): each
// kernel stores E5 = erode(img_after_step4); the next kernel loads it as E1.
// INIT: load raw, full chain X,E1..E5 (5 erodes), store E5 (66-pitch).
// else: loaded X IS E1; chain E2..E5 (4 erodes), store E5 (68-pitch, aligned).
// ---------------------------------------------------------------------------
template<bool BORDER, bool RED, bool INIT>
__device__ __forceinline__ void fused_body(const float* __restrict__ sp,
                                           const float* __restrict__ raw,
                                           float* __restrict__ dp,
                                           const float* __restrict__ yt,
                                           const float* __restrict__ yp,
                                           float* sX, float* sY, float* s_red,
                                           int plane, int by, int bx, int tid) {
    const int tx = tid & 31, ty = tid >> 5;

    // Load with halo 6 into sX (pitch 76).
    if (INIT) {
        for (int r = ty; r < 76; r += 8) {
            float* srow = sX + r * 76;
            const int gr = by + r - 6;
            if (!BORDER) {
                const float* grp = raw + gr * W + bx - 6;
                *(float2*)(srow + 2 * tx) = *(const float2*)(grp + 2 * tx);
                if (tx < 6) *(float2*)(srow + 64 + 2 * tx) = *(const float2*)(grp + 64 + 2 * tx);
            } else {
                const bool rok = (unsigned)gr < 512u;
                {
                    const int gc = bx + 2 * tx - 6;
                    float v0 = BIGF, v1 = BIGF;
                    if (rok) {
                        if ((unsigned)gc < 512u) v0 = raw[gr * W + gc];
                        if ((unsigned)(gc + 1) < 512u) v1 = raw[gr * W + gc + 1];
                    }
                    *(float2*)(srow + 2 * tx) = make_float2(v0, v1);
                }
                if (tx < 6) {
                    const int gc = bx + 58 + 2 * tx;
                    float v0 = BIGF, v1 = BIGF;
                    if (rok) {
                        if ((unsigned)gc < 512u) v0 = raw[gr * W + gc];
                        if ((unsigned)(gc + 1) < 512u) v1 = raw[gr * W + gc + 1];
                    }
                    *(float2*)(srow + 64 + 2 * tx) = make_float2(v0, v1);
                }
            }
        }
    } else {
        const float* g0 = sp + (by - 6) * GP + (bx - 6);
        for (int r = ty; r < 76; r += 8) {
            const float2* grp = (const float2*)(g0 + r * GP);
            float2* srow = (float2*)(sX + r * 76);
            srow[tx] = grp[tx];
            if (tx < 6) srow[tx + 32] = grp[tx + 32];
        }
    }
    __syncthreads();

    // First erode: INIT: E1 = erode(X); else: E2 = erode(E1).
    erode_pair<76, 5, BORDER>(sX, sY, by, bx, tx, ty, tid);
    __syncthreads();

    float2 sk[8];
    const int r0 = ty * 8, j = 2 * tx;

    if (INIT) {
        // init skel = gelu(X - dilate(E1))
        upd_pair<76, 6, BORDER, true>(sX, sY, sk, by, bx, tx, ty);
        __syncthreads();
        erode_pair<74, 4, BORDER>(sY, sX, by, bx, tx, ty, tid);   // E2 (72, h4)
        __syncthreads();
        upd_pair<74, 5, BORDER, false>(sY, sX, sk, by, bx, tx, ty);   // step 1
        __syncthreads();
        erode_pair<72, 3, BORDER>(sX, sY, by, bx, tx, ty, tid);   // E3 (70, h3)
        __syncthreads();
        upd_pair<72, 4, BORDER, false>(sX, sY, sk, by, bx, tx, ty);   // step 2
        __syncthreads();
        erode_pair<70, 2, BORDER>(sY, sX, by, bx, tx, ty, tid);   // E4 (68, h2)
        __syncthreads();
        upd_pair<70, 3, BORDER, false>(sY, sX, sk, by, bx, tx, ty);   // step 3
        __syncthreads();
        erode_pair<68, 1, BORDER>(sX, sY, by, bx, tx, ty, tid);   // E5 (66, h1)
        __syncthreads();
        upd_pair<68, 2, BORDER, false>(sX, sY, sk, by, bx, tx, ty);   // step 4

        // store skel + E5 center (sY, pitch 66, center odd -> 2 scalar LDS)
        float* gs = &g_skel[plane * PLANE + (by + r0) * W + bx + j];
        float* gd = dp + (by + r0) * GP + bx + j;
        #pragma unroll
        for (int q = 0; q < 8; ++q) {
            *(float2*)(gs + q * W) = sk[q];
            const float v0 = sY[(r0 + q + 1) * 66 + j + 1];
            const float v1 = sY[(r0 + q + 1) * 66 + j + 2];
            *(float2*)(gd + q * GP) = make_float2(v0, v1);
        }
    } else {
        // loaded image is E1 (halo 6). sY now holds E2 (74, h5).
        const float* gs0 = &g_skel[plane * PLANE + (by + r0) * W + bx + j];
        #pragma unroll
        for (int q = 0; q < 8; ++q) sk[q] = *(const float2*)(gs0 + q * W);

        upd_pair<76, 6, BORDER, false>(sX, sY, sk, by, bx, tx, ty);   // step 1 (E1,E2)
        __syncthreads();
        erode_pair<74, 4, BORDER>(sY, sX, by, bx, tx, ty, tid);   // E3 (72, h4)
        __syncthreads();
        upd_pair<74, 5, BORDER, false>(sY, sX, sk, by, bx, tx, ty);   // step 2 (E2,E3)
        __syncthreads();
        erode_pair<72, 3, BORDER>(sX, sY, by, bx, tx, ty, tid);   // E4 (70, h3)
        __syncthreads();
        upd_pair<72, 4, BORDER, false>(sX, sY, sk, by, bx, tx, ty);   // step 3 (E3,E4)
        __syncthreads();
        erode_pair<70, 2, BORDER>(sY, sX, by, bx, tx, ty, tid);   // E5 (68, h2)
        __syncthreads();
        upd_pair<70, 3, BORDER, false>(sY, sX, sk, by, bx, tx, ty);   // step 4 (E4,E5)

        if (!RED) {
            // store skel + E5 center (sX, pitch 68, center even -> aligned)
            float* gs = &g_skel[plane * PLANE + (by + r0) * W + bx + j];
            float* gd = dp + (by + r0) * GP + bx + j;
            #pragma unroll
            for (int q = 0; q < 8; ++q) {
                *(float2*)(gs + q * W) = sk[q];
                *(float2*)(gd + q * GP) = *(const float2*)(sX + (r0 + q + 2) * 68 + j + 2);
            }
        } else {
            float a0 = 0.f, a1 = 0.f, a2 = 0.f, a3 = 0.f, a4 = 0.f, a5 = 0.f, a6 = 0.f;
            const int gi0 = (plane & 15) * PLANE + (by + r0) * W + bx + j;
            if (plane < HALF) {
                #pragma unroll
                for (int q = 0; q < 8; ++q) {
                    const float2 t = *(const float2*)(yt + gi0 + q * W);
                    const float2 p = *(const float2*)(yp + gi0 + q * W);
                    const float2 s = sk[q];
                    a0 += t.x + t.y;
                    a1 += p.x + p.y;
                    a2 += t.x * p.x + t.y * p.y;
                    a3 += s.x + s.y;
                    a4 += s.x * t.x + s.y * t.y;
                }
            } else {
                #pragma unroll
                for (int q = 0; q < 8; ++q) {
                    const float2 p = *(const float2*)(yp + gi0 + q * W);
                    const float2 s = sk[q];
                    a5 += s.x + s.y;
                    a6 += s.x * p.x + s.y * p.y;
                }
            }
            float v[7] = {a0, a1, a2, a3, a4, a5, a6};
            const int lane = tid & 31, wrp = tid >> 5;
            #pragma unroll
            for (int k = 0; k < 7; k++) {
                const float s = warpSum(v[k]);
                if (lane == 0) s_red[wrp * 8 + k] = s;
            }
            __syncthreads();
            if (wrp == 0) {
                const int bid = plane * 64 + (by >> 6) * 8 + (bx >> 6);
                #pragma unroll
                for (int k = 0; k < 7; k++) {
                    float s = (lane < 8) ? s_red[lane * 8 + k] : 0.f;
                    s = warpSum(s);
                    if (lane == 0) g_part[bid * 8 + k] = s;
                }
            }
        }
    }
}

// ---------------------------------------------------------------------------
// Kernel wrappers
// ---------------------------------------------------------------------------
__global__ __launch_bounds__(NT, 5) void fused_init_kernel(const float* __restrict__ yt,
                                                           const float* __restrict__ yp) {
    __shared__ __align__(16) float sX[76 * 76];
    __shared__ __align__(16) float sY[74 * 74];
    const int plane = blockIdx.z;
    const float* raw = ((plane < HALF) ? yp : yt) + (plane & 15) * PLANE;
    const int by = blockIdx.y * 64, bx = blockIdx.x * 64;
    float* dp = g_bufA + plane * PSZ + BOFF;
    const bool border = (blockIdx.x == 0) | (blockIdx.x == 7) | (blockIdx.y == 0) | (blockIdx.y == 7);
    if (border) fused_body<true , false, true>(nullptr, raw, dp, nullptr, nullptr, sX, sY, nullptr,
                                               plane, by, bx, threadIdx.x);
    else        fused_body<false, false, true>(nullptr, raw, dp, nullptr, nullptr, sX, sY, nullptr,
                                               plane, by, bx, threadIdx.x);
}

__global__ __launch_bounds__(NT, 5) void fused_kernel(int readA) {
    __shared__ __align__(16) float sX[76 * 76];
    __shared__ __align__(16) float sY[74 * 74];
    const float* src = readA ? g_bufA : g_bufB;
    float* dst = readA ? g_bufB : g_bufA;
    const int plane = blockIdx.z;
    const int by = blockIdx.y * 64, bx = blockIdx.x * 64;
    const float* sp = src + plane * PSZ + BOFF;
    float* dp = dst + plane * PSZ + BOFF;
    const bool border = (blockIdx.x == 0) | (blockIdx.x == 7) | (blockIdx.y == 0) | (blockIdx.y == 7);
    if (border) fused_body<true , false, false>(sp, nullptr, dp, nullptr, nullptr, sX, sY, nullptr,
                                                plane, by, bx, threadIdx.x);
    else        fused_body<false, false, false>(sp, nullptr, dp, nullptr, nullptr, sX, sY, nullptr,
                                                plane, by, bx, threadIdx.x);
}

__global__ __launch_bounds__(NT, 5) void fused_red_kernel(const float* __restrict__ yt,
                                                          const float* __restrict__ yp,
                                                          int readA) {
    __shared__ __align__(16) float sX[76 * 76];
    __shared__ __align__(16) float sY[74 * 74];
    __shared__ float s_red[64];
    const float* src = readA ? g_bufA : g_bufB;
    float* dst = readA ? g_bufB : g_bufA;
    const int plane = blockIdx.z;
    const int by = blockIdx.y * 64, bx = blockIdx.x * 64;
    const float* sp = src + plane * PSZ + BOFF;
    float* dp = dst + plane * PSZ + BOFF;
    const bool border = (blockIdx.x == 0) | (blockIdx.x == 7) | (blockIdx.y == 0) | (blockIdx.y == 7);
    if (border) fused_body<true , true, false>(sp, nullptr, dp, yt, yp, sX, sY, s_red,
                                               plane, by, bx, threadIdx.x);
    else        fused_body<false, true, false>(sp, nullptr, dp, yt, yp, sX, sY, s_red,
                                               plane, by, bx, threadIdx.x);
}

// ---------------------------------------------------------------------------
// Final: sum 2048 partials, compute loss scalar
// ---------------------------------------------------------------------------
__global__ __launch_bounds__(256) void final_kernel(float* __restrict__ out) {
    float a[7] = {0.f, 0.f, 0.f, 0.f, 0.f, 0.f, 0.f};
    for (int b = threadIdx.x; b < NBLOCKS; b += 256) {
        #pragma unroll
        for (int j = 0; j < 7; j++) a[j] += g_part[b * 8 + j];
    }
    __shared__ float shm[8][8];
    const int lane = threadIdx.x & 31, wrp = threadIdx.x >> 5;
    #pragma unroll
    for (int j = 0; j < 7; j++) {
        const float v = warpSum(a[j]);
        if (lane == 0) shm[wrp][j] = v;
    }
    __syncthreads();
    if (wrp == 0) {
        float res[7];
        #pragma unroll
        for (int j = 0; j < 7; j++) {
            float v = (lane < 8) ? shm[lane][j] : 0.f;
            res[j] = warpSum(v);
        }
        if (lane == 0) {
            const float S_t = res[0], S_p = res[1], S_tp = res[2];
            const float S_sp = res[3], S_spt = res[4];
            const float S_st = res[5], S_stp = res[6];
            const float dice  = 1.0f - (2.0f * S_tp + 1.0f) / (S_t + S_p + 1.0f);
            const float tprec = (S_spt + 1.0f) / (S_sp + 1.0f);
            const float tsens = (S_stp + 1.0f) / (S_st + 1.0f);
            const float cl    = 1.0f - 2.0f * (tprec * tsens) / (tprec + tsens);
            out[0] = 0.7f * dice + 0.3f * cl;
        }
    }
}

// ---------------------------------------------------------------------------
extern "C" void kernel_launch(void* const* d_in, const int* in_sizes, int n_in,
                              void* d_out, int out_size) {
    const float* y_true = (const float*)d_in[0];
    const float* y_pred = (const float*)d_in[1];

    dim3 grid(8, 8, NPLANES);
    dim3 blk(NT);

    fill_ring_kernel<<<dim3(GR, NPLANES, 2), 64>>>();
    fused_init_kernel<<<grid, blk>>>(y_true, y_pred);    // init + steps 1-4, store E5 -> A
    fused_kernel<<<grid, blk>>>(1);                      // steps 5-8   A -> B
    fused_kernel<<<grid, blk>>>(0);                      // steps 9-12  B -> A
    fused_kernel<<<grid, blk>>>(1);                      // steps 13-16 A -> B
    fused_red_kernel<<<grid, blk>>>(y_true, y_pred, 0);  // steps 17-20 + sums (reads B)
    final_kernel<<<1, 256>>>((float*)d_out);
}